// round 2
// baseline (speedup 1.0000x reference)
#include <cuda_runtime.h>

// Problem constants
#define HID 100          // hidden size
#define G4  400          // 4 * HID gates
#define TT  128          // timesteps
#define NSEQ 12288       // 4096 cells * 3 sub-sequences
#define SEQ_PER_CTA 32
#define NTHREADS 800     // 100 j-slots * 8 seq-quads  (= 25 warps exactly)
#define HS_STRIDE 68     // padded h row stride (odd multiple of 4 floats -> conflict-free STS.128)

#define SMEM_FLOATS (HID * G4 + HID * HS_STRIDE)   // 40000 + 6800 = 46800
#define SMEM_BYTES  (SMEM_FLOATS * 4)              // 187200

// Packed weights (written by pack_kernel every launch; deterministic)
__device__ float g_Wt[HID * G4];    // [k][j][gate] : W_hh[gate*100+j][k]
__device__ float g_bias4[G4];       // [j][gate]    : b_ih + b_hh
__device__ float g_Wx4[HID * 16];   // [j][f][gate] : W_ih[gate*100+j][f]

__global__ void pack_kernel(const float* __restrict__ W_ih,
                            const float* __restrict__ W_hh,
                            const float* __restrict__ b_ih,
                            const float* __restrict__ b_hh) {
    int idx = blockIdx.x * blockDim.x + threadIdx.x;
    if (idx < HID * G4) {
        int k = idx / G4;
        int rem = idx % G4;
        int j = rem >> 2;
        int q = rem & 3;
        g_Wt[idx] = W_hh[(q * HID + j) * HID + k];
    }
    if (idx < G4) {
        int j = idx >> 2, q = idx & 3;
        g_bias4[idx] = b_ih[q * HID + j] + b_hh[q * HID + j];
    }
    if (idx < HID * 16) {
        int j = idx >> 4;
        int f = (idx >> 2) & 3;
        int q = idx & 3;
        g_Wx4[idx] = W_ih[(q * HID + j) * 4 + f];
    }
}

__device__ __forceinline__ float fsigmoid(float v) {
    return 1.0f / (1.0f + __expf(-v));
}
// tanh(x) = 1 - 2/(exp(2x)+1); handles +-inf saturation correctly
__device__ __forceinline__ float ftanh(float v) {
    return 1.0f - 2.0f / (1.0f + __expf(2.0f * v));
}

extern __shared__ float smem[];

__global__ void __launch_bounds__(NTHREADS, 1)
lstm_kernel(const float* __restrict__ x,   // [NSEQ][TT][4]
            float* __restrict__ out)       // [NSEQ][HID]
{
    float* Wts = smem;                 // [k][j][gate] 100*400
    float* hs  = smem + HID * G4;      // [k][seq] rows of HS_STRIDE

    const int tid  = threadIdx.x;
    const int seq0 = blockIdx.x * SEQ_PER_CTA;
    const int j = tid % HID;           // hidden unit index
    const int q = tid / HID;           // seq-quad index, 0..7

    // Cooperative copy of packed W_hh into smem (float4)
    {
        const float4* src = (const float4*)g_Wt;
        float4* dst = (float4*)Wts;
        for (int i = tid; i < (HID * G4) / 4; i += NTHREADS) dst[i] = src[i];
    }
    // Zero h state
    for (int i = tid; i < HID * HS_STRIDE; i += NTHREADS) hs[i] = 0.0f;

    // Per-thread constants
    const float4 bias = *(const float4*)&g_bias4[j * 4];
    float4 wxf[4];
#pragma unroll
    for (int f = 0; f < 4; ++f) wxf[f] = *(const float4*)&g_Wx4[j * 16 + f * 4];

    __syncthreads();

    float c[4] = {0.f, 0.f, 0.f, 0.f};
    float hnew[4] = {0.f, 0.f, 0.f, 0.f};
    const float* xbase = x + (size_t)(seq0 + q * 4) * (TT * 4);

    for (int t = 0; t < TT; ++t) {
        // gate pre-activations: bias + x @ W_ih^T  (F = 4)
        float ai[4], af[4], ag[4], ao[4];
#pragma unroll
        for (int s = 0; s < 4; ++s) {
            float4 xv = *(const float4*)(xbase + (size_t)s * (TT * 4) + t * 4);
            ai[s] = bias.x + wxf[0].x * xv.x + wxf[1].x * xv.y + wxf[2].x * xv.z + wxf[3].x * xv.w;
            af[s] = bias.y + wxf[0].y * xv.x + wxf[1].y * xv.y + wxf[2].y * xv.z + wxf[3].y * xv.w;
            ag[s] = bias.z + wxf[0].z * xv.x + wxf[1].z * xv.y + wxf[2].z * xv.z + wxf[3].z * xv.w;
            ao[s] = bias.w + wxf[0].w * xv.x + wxf[1].w * xv.y + wxf[2].w * xv.z + wxf[3].w * xv.w;
        }

        // recurrent part: += W_hh[gate*100+j][k] * h[seq][k]
        const float* wp = Wts + j * 4;
        const float* hp = hs + q * 4;
#pragma unroll 4
        for (int k = 0; k < HID; ++k) {
            float4 wv = *(const float4*)(wp + k * G4);        // 4 gates for unit j
            float4 hv = *(const float4*)(hp + k * HS_STRIDE); // 4 seqs, unit k
            ai[0] += wv.x * hv.x; af[0] += wv.y * hv.x; ag[0] += wv.z * hv.x; ao[0] += wv.w * hv.x;
            ai[1] += wv.x * hv.y; af[1] += wv.y * hv.y; ag[1] += wv.z * hv.y; ao[1] += wv.w * hv.y;
            ai[2] += wv.x * hv.z; af[2] += wv.y * hv.z; ag[2] += wv.z * hv.z; ao[2] += wv.w * hv.z;
            ai[3] += wv.x * hv.w; af[3] += wv.y * hv.w; ag[3] += wv.z * hv.w; ao[3] += wv.w * hv.w;
        }
        __syncthreads();   // all reads of h(t-1) complete

#pragma unroll
        for (int s = 0; s < 4; ++s) {
            float ig = fsigmoid(ai[s]);
            float fg = fsigmoid(af[s]);
            float gg = ftanh(ag[s]);
            float og = fsigmoid(ao[s]);
            c[s] = fg * c[s] + ig * gg;
            hnew[s] = og * ftanh(c[s]);
        }
        *(float4*)(hs + j * HS_STRIDE + q * 4) =
            make_float4(hnew[0], hnew[1], hnew[2], hnew[3]);
        __syncthreads();   // h(t) visible to all
    }

#pragma unroll
    for (int s = 0; s < 4; ++s)
        out[(size_t)(seq0 + q * 4 + s) * HID + j] = hnew[s];
}

extern "C" void kernel_launch(void* const* d_in, const int* in_sizes, int n_in,
                              void* d_out, int out_size) {
    const float* x    = (const float*)d_in[0];  // short_ttf [4096,3,128,4]
    const float* W_ih = (const float*)d_in[1];  // [400,4]
    const float* W_hh = (const float*)d_in[2];  // [400,100]
    const float* b_ih = (const float*)d_in[3];  // [400]
    const float* b_hh = (const float*)d_in[4];  // [400]
    float* out = (float*)d_out;                 // [4096,300] == [12288,100]

    pack_kernel<<<(HID * G4 + 255) / 256, 256>>>(W_ih, W_hh, b_ih, b_hh);

    cudaFuncSetAttribute(lstm_kernel,
                         cudaFuncAttributeMaxDynamicSharedMemorySize, SMEM_BYTES);
    lstm_kernel<<<NSEQ / SEQ_PER_CTA, NTHREADS, SMEM_BYTES>>>(x, out);
}

// round 3
// speedup vs baseline: 1.0532x; 1.0532x over previous
#include <cuda_runtime.h>

#define HID 100          // hidden size
#define G4  400          // 4 * HID
#define TT  128          // timesteps
#define NSEQ 12288       // 4096 cells * 3
#define SEQ_PER_CTA 48
#define NCTAS (NSEQ / SEQ_PER_CTA)   // 256
#define NTHREADS 800     // 100 j-slots * 8 groups (25 warps)
#define HS_STRIDE 68     // padded h row stride (floats)

// smem layout (float offsets)
#define OFF_W    0
#define OFF_WX   (HID * G4)                   // 40000
#define OFF_BIAS (OFF_WX + HID * 16)          // 41600
#define OFF_H0   (OFF_BIAS + G4)              // 42000
#define OFF_H1   (OFF_H0 + HID * HS_STRIDE)   // 48800
#define SMEM_FLOATS (OFF_H1 + HID * HS_STRIDE) // 55600
#define SMEM_BYTES (SMEM_FLOATS * 4)           // 222400

typedef unsigned long long ull;

// Packed weights (written by pack_kernel every launch; deterministic)
__device__ float g_Wt[HID * G4];    // [k][j][gate] : W_hh[gate*100+j][k]
__device__ float g_bias4[G4];       // [j][gate]    : b_ih + b_hh
__device__ float g_Wx4[HID * 16];   // [j][f][gate] : W_ih[gate*100+j][f]

__global__ void pack_kernel(const float* __restrict__ W_ih,
                            const float* __restrict__ W_hh,
                            const float* __restrict__ b_ih,
                            const float* __restrict__ b_hh) {
    int idx = blockIdx.x * blockDim.x + threadIdx.x;
    if (idx < HID * G4) {
        int k = idx / G4;
        int rem = idx % G4;
        int j = rem >> 2;
        int q = rem & 3;
        g_Wt[idx] = W_hh[(q * HID + j) * HID + k];
    }
    if (idx < G4) {
        int j = idx >> 2, q = idx & 3;
        g_bias4[idx] = b_ih[q * HID + j] + b_hh[q * HID + j];
    }
    if (idx < HID * 16) {
        int j = idx >> 4;
        int f = (idx >> 2) & 3;
        int q = idx & 3;
        g_Wx4[idx] = W_ih[(q * HID + j) * 4 + f];
    }
}

__device__ __forceinline__ float fsigmoid(float v) {
    return 1.0f / (1.0f + __expf(-v));
}
__device__ __forceinline__ float ftanh(float v) {
    return 1.0f - 2.0f / (1.0f + __expf(2.0f * v));
}

// f32x2 packed helpers (sm_103a FFMA2 path)
__device__ __forceinline__ ull pk2(float a, float b) {
    ull r;
    asm("mov.b64 %0, {%1, %2};" : "=l"(r) : "f"(a), "f"(b));
    return r;
}
__device__ __forceinline__ ull dup2(float a) {
    ull r;
    asm("mov.b64 %0, {%1, %1};" : "=l"(r) : "f"(a));
    return r;
}
__device__ __forceinline__ float2 upk2(ull v) {
    float2 r;
    asm("mov.b64 {%0, %1}, %2;" : "=f"(r.x), "=f"(r.y) : "l"(v));
    return r;
}
__device__ __forceinline__ ull ffma2(ull a, ull b, ull c) {
    ull d;
    asm("fma.rn.f32x2 %0, %1, %2, %3;" : "=l"(d) : "l"(a), "l"(b), "l"(c));
    return d;
}

extern __shared__ float smem[];

__global__ void __launch_bounds__(NTHREADS, 1)
lstm_kernel(const float* __restrict__ x,   // [NSEQ][TT][4]
            float* __restrict__ out)       // [NSEQ][HID]
{
    float* Ws   = smem + OFF_W;
    float* Wxs  = smem + OFF_WX;
    float* Bs   = smem + OFF_BIAS;
    float* hb0  = smem + OFF_H0;
    float* hb1  = smem + OFF_H1;

    const int tid  = threadIdx.x;
    const int j = tid % HID;           // hidden unit
    const int g = tid / HID;           // seq group 0..7, 6 seqs each

    // Cooperative smem fills
    {
        const float4* src = (const float4*)g_Wt;
        float4* dst = (float4*)Ws;
        for (int i = tid; i < (HID * G4) / 4; i += NTHREADS) dst[i] = src[i];
    }
    for (int i = tid; i < HID * 16; i += NTHREADS) Wxs[i] = g_Wx4[i];
    for (int i = tid; i < G4; i += NTHREADS)       Bs[i]  = g_bias4[i];
    // zero the t=0 read buffer
    for (int i = tid; i < HID * HS_STRIDE; i += NTHREADS) hb0[i] = 0.0f;
    __syncthreads();

    float c[6] = {0.f, 0.f, 0.f, 0.f, 0.f, 0.f};
    float hlast[6];
    const int seq0 = blockIdx.x * SEQ_PER_CTA + g * 6;
    const float* xb = x + (size_t)seq0 * (TT * 4);

    for (int t = 0; t < TT; ++t) {
        // ---- x phase: pre[gate][s] = bias + x_t . W_ih ----
        float4 bias = *(const float4*)&Bs[j * 4];
        float4 wx0 = *(const float4*)&Wxs[j * 16 + 0];
        float4 wx1 = *(const float4*)&Wxs[j * 16 + 4];
        float4 wx2 = *(const float4*)&Wxs[j * 16 + 8];
        float4 wx3 = *(const float4*)&Wxs[j * 16 + 12];

        float pi[6], pf[6], pg[6], po[6];
#pragma unroll
        for (int s = 0; s < 6; ++s) {
            float4 xv = *(const float4*)(xb + (size_t)s * (TT * 4) + t * 4);
            pi[s] = bias.x + wx0.x * xv.x + wx1.x * xv.y + wx2.x * xv.z + wx3.x * xv.w;
            pf[s] = bias.y + wx0.y * xv.x + wx1.y * xv.y + wx2.y * xv.z + wx3.y * xv.w;
            pg[s] = bias.z + wx0.z * xv.x + wx1.z * xv.y + wx2.z * xv.z + wx3.z * xv.w;
            po[s] = bias.w + wx0.w * xv.x + wx1.w * xv.y + wx2.w * xv.z + wx3.w * xv.w;
        }

        // packed accumulators: [gate][pair] over 3 seq-pairs
        ull ai0 = pk2(pi[0], pi[1]), ai1 = pk2(pi[2], pi[3]), ai2 = pk2(pi[4], pi[5]);
        ull af0 = pk2(pf[0], pf[1]), af1 = pk2(pf[2], pf[3]), af2 = pk2(pf[4], pf[5]);
        ull ag0 = pk2(pg[0], pg[1]), ag1 = pk2(pg[2], pg[3]), ag2 = pk2(pg[4], pg[5]);
        ull ao0 = pk2(po[0], po[1]), ao1 = pk2(po[2], po[3]), ao2 = pk2(po[4], po[5]);

        const float* hr = (t & 1) ? hb1 : hb0;
        float*       hw = (t & 1) ? hb0 : hb1;

        // ---- recurrent phase: FFMA2 over k ----
        const float* wp = Ws + j * 4;
        const float* hp = hr + g * 8;
#pragma unroll 2
        for (int k = 0; k < HID; ++k) {
            float4 wv = *(const float4*)(wp + k * G4);   // (wi,wf,wg,wo) for unit j
            ull wi = dup2(wv.x), wf = dup2(wv.y), wg = dup2(wv.z), wo = dup2(wv.w);
            const float* hk = hp + k * HS_STRIDE;
            ulonglong2 hAB = *(const ulonglong2*)hk;     // (h0,h1),(h2,h3)
            ull hC = *(const ull*)(hk + 4);              // (h4,h5)
            ai0 = ffma2(wi, hAB.x, ai0); ai1 = ffma2(wi, hAB.y, ai1); ai2 = ffma2(wi, hC, ai2);
            af0 = ffma2(wf, hAB.x, af0); af1 = ffma2(wf, hAB.y, af1); af2 = ffma2(wf, hC, af2);
            ag0 = ffma2(wg, hAB.x, ag0); ag1 = ffma2(wg, hAB.y, ag1); ag2 = ffma2(wg, hC, ag2);
            ao0 = ffma2(wo, hAB.x, ao0); ao1 = ffma2(wo, hAB.y, ao1); ao2 = ffma2(wo, hC, ao2);
        }

        // ---- activations ----
        float ii[6], ff[6], gg[6], oo[6];
        {
            float2 u;
            u = upk2(ai0); ii[0]=u.x; ii[1]=u.y;
            u = upk2(ai1); ii[2]=u.x; ii[3]=u.y;
            u = upk2(ai2); ii[4]=u.x; ii[5]=u.y;
            u = upk2(af0); ff[0]=u.x; ff[1]=u.y;
            u = upk2(af1); ff[2]=u.x; ff[3]=u.y;
            u = upk2(af2); ff[4]=u.x; ff[5]=u.y;
            u = upk2(ag0); gg[0]=u.x; gg[1]=u.y;
            u = upk2(ag1); gg[2]=u.x; gg[3]=u.y;
            u = upk2(ag2); gg[4]=u.x; gg[5]=u.y;
            u = upk2(ao0); oo[0]=u.x; oo[1]=u.y;
            u = upk2(ao1); oo[2]=u.x; oo[3]=u.y;
            u = upk2(ao2); oo[4]=u.x; oo[5]=u.y;
        }
#pragma unroll
        for (int s = 0; s < 6; ++s) {
            float ig = fsigmoid(ii[s]);
            float fg = fsigmoid(ff[s]);
            float tg = ftanh(gg[s]);
            float og = fsigmoid(oo[s]);
            c[s] = fg * c[s] + ig * tg;
            hlast[s] = og * ftanh(c[s]);
        }

        // ---- publish h(t) to the write buffer ----
        float* dst = hw + j * HS_STRIDE + g * 8;
        *(float4*)dst       = make_float4(hlast[0], hlast[1], hlast[2], hlast[3]);
        *(float2*)(dst + 4) = make_float2(hlast[4], hlast[5]);
        __syncthreads();
    }

#pragma unroll
    for (int s = 0; s < 6; ++s)
        out[(size_t)(seq0 + s) * HID + j] = hlast[s];
}

extern "C" void kernel_launch(void* const* d_in, const int* in_sizes, int n_in,
                              void* d_out, int out_size) {
    const float* x    = (const float*)d_in[0];  // short_ttf [4096,3,128,4]
    const float* W_ih = (const float*)d_in[1];  // [400,4]
    const float* W_hh = (const float*)d_in[2];  // [400,100]
    const float* b_ih = (const float*)d_in[3];  // [400]
    const float* b_hh = (const float*)d_in[4];  // [400]
    float* out = (float*)d_out;                 // [4096,300] == [12288,100]

    pack_kernel<<<(HID * G4 + 255) / 256, 256>>>(W_ih, W_hh, b_ih, b_hh);

    cudaFuncSetAttribute(lstm_kernel,
                         cudaFuncAttributeMaxDynamicSharedMemorySize, SMEM_BYTES);
    lstm_kernel<<<NCTAS, NTHREADS, SMEM_BYTES>>>(x, out);
}